// round 5
// baseline (speedup 1.0000x reference)
#include <cuda_runtime.h>
#include <cuda_bf16.h>

#define Bv 4
#define Tv 512
#define Iv 512
#define Hv 8
#define Dv 512
#define Vv 32000
#define NCHUNK 2                 // stream blocks per row
#define CHUNK  (Vv / NCHUNK)     // 16000 floats per chunk
#define HSZ 1024                 // dedup hash table slots

// scratch (allocation-free rule: __device__ globals)
__device__ int   g_leader[Bv * Iv];
__device__ float g_encW[Bv * Iv];
__device__ int   g_nu[Bv];
__device__ float g_pg[Bv * Tv];
__device__ float g_base[Bv * Tv];
__device__ float g_eb[Bv * Tv * Iv];   // e*base per (row, slot-owner i); 4MB

// ---------------------------------------------------------------------------
// Prep: blocks [0,512) encW (4 warps/block, one (b,i) row per warp, float4);
// blocks [512,516) per-batch dedup via smem hash.
// ---------------------------------------------------------------------------
__global__ __launch_bounds__(128) void prep_kernel(const int* __restrict__ tok,
                                                   const float* __restrict__ enc,
                                                   const float* __restrict__ W) {
    if (blockIdx.x < 512) {
        int warp = blockIdx.x * 4 + (threadIdx.x >> 5);    // 0..2047 = b*I+i
        int lane = threadIdx.x & 31;
        const float4* row = (const float4*)(enc + (long)warp * Dv);
        const float4* W4  = (const float4*)W;
        float acc = 0.f;
        #pragma unroll
        for (int k = 0; k < 4; k++) {
            int q = lane + 32 * k;              // 128 float4 per row
            float4 r = __ldg(&row[q]);
            float4 w = __ldg(&W4[q]);
            acc = fmaf(r.x, w.x, acc);
            acc = fmaf(r.y, w.y, acc);
            acc = fmaf(r.z, w.z, acc);
            acc = fmaf(r.w, w.w, acc);
        }
        #pragma unroll
        for (int o = 16; o; o >>= 1) acc += __shfl_down_sync(0xffffffffu, acc, o);
        if (lane == 0) g_encW[warp] = acc;
    } else {
        __shared__ int hkey[HSZ];
        __shared__ int hval[HSZ];
        __shared__ int cnt;
        int b = blockIdx.x - 512;
        int tid = threadIdx.x;
        if (tid == 0) cnt = 0;
        #pragma unroll
        for (int s = tid; s < HSZ; s += 128) { hkey[s] = -1; hval[s] = 0x7fffffff; }
        __syncthreads();
        int myslot[4], mytok[4];
        #pragma unroll
        for (int k = 0; k < 4; k++) {
            int i = tid + 128 * k;
            int me = tok[b * Iv + i];
            mytok[k] = me;
            unsigned h = ((unsigned)me * 2654435761u) & (HSZ - 1);
            while (true) {
                int kk = atomicCAS(&hkey[h], -1, me);
                if (kk == -1 || kk == me) break;
                h = (h + 1) & (HSZ - 1);
            }
            myslot[k] = (int)h;
            atomicMin(&hval[h], i);
        }
        __syncthreads();
        int local = 0;
        #pragma unroll
        for (int k = 0; k < 4; k++) {
            int i = tid + 128 * k;
            int lead = hval[myslot[k]];
            g_leader[b * Iv + i] = lead;
            if (lead == i) local++;
        }
        atomicAdd(&cnt, local);
        __syncthreads();
        if (tid == 0) g_nu[b] = cnt;
    }
}

// ---------------------------------------------------------------------------
// Dual block reduction: sums v1 and v2 across 512 threads with one barrier set.
// ---------------------------------------------------------------------------
__device__ __forceinline__ void block_reduce_sum2(float v1, float v2,
                                                  float* s1, float* s2,
                                                  float& r1, float& r2) {
    int lane = threadIdx.x & 31;
    int w = threadIdx.x >> 5;
    #pragma unroll
    for (int o = 16; o; o >>= 1) {
        v1 += __shfl_down_sync(0xffffffffu, v1, o);
        v2 += __shfl_down_sync(0xffffffffu, v2, o);
    }
    if (lane == 0) { s1[w] = v1; s2[w] = v2; }
    __syncthreads();
    if (w == 0) {
        float x1 = (lane < 16) ? s1[lane] : 0.f;
        float x2 = (lane < 16) ? s2[lane] : 0.f;
        #pragma unroll
        for (int o = 8; o; o >>= 1) {
            x1 += __shfl_down_sync(0xffffffffu, x1, o);
            x2 += __shfl_down_sync(0xffffffffu, x2, o);
        }
        if (lane == 0) { s1[0] = x1; s2[0] = x2; }
    }
    __syncthreads();
    r1 = s1[0];
    r2 = s2[0];
}

// ---------------------------------------------------------------------------
// Row kernel: all latency/reduction work per (b,t) row; no bulk streaming.
// ---------------------------------------------------------------------------
__global__ __launch_bounds__(512) void row_kernel(
    const int* __restrict__ tok,
    const float* __restrict__ tar,
    const float* __restrict__ dec,
    const float* __restrict__ attn_heads,
    const float* __restrict__ W,
    const float* __restrict__ bpg,
    float* __restrict__ out)
{
    const int row = blockIdx.x;        // b*T + t
    const int b   = row >> 9;
    const int t   = row & 511;
    const int tid = threadIdx.x;

    __shared__ float ss[Iv];
    __shared__ float s1[32], s2[32];

    const int lead = g_leader[b * Iv + tid];
    ss[tid] = 0.f;

    // head-mean attention weight for column i = tid
    float w = 0.f;
    long base_a = ((long)b * Hv) * ((long)Tv * Iv) + (long)t * Iv + tid;
    #pragma unroll
    for (int h = 0; h < Hv; h++) w += attn_heads[base_a + (long)h * Tv * Iv];
    w *= 0.125f;

    __syncthreads();                   // ss zeroed
    atomicAdd(&ss[lead], w);

    // p_gen partials overlap the atomics
    float acc = w * g_encW[b * Iv + tid];
    acc = fmaf(dec[(long)row * Dv + tid], W[Dv + tid], acc);
    acc = fmaf(tar[(long)row * Dv + tid], W[2 * Dv + tid], acc);

    __syncthreads();                   // publish atomics

    const bool active = (lead == tid);
    float e = active ? expf(ss[tid]) : 0.f;

    float pgsum, esum;
    block_reduce_sum2(acc, e, s1, s2, pgsum, esum);

    const float denom = esum + (float)(Vv - g_nu[b]);
    const float base  = 1.f / denom;
    const float pg    = 1.f / (1.f + expf(-(pgsum + bpg[0])));

    g_eb[(long)row * Iv + tid] = e * base;     // 0 for inactive slots
    if (tid == 0) {
        g_pg[row]   = pg;
        g_base[row] = base;
        out[2L * Bv * Tv * Vv + row] = pg;     // p_gen (B,T)
    }
}

// ---------------------------------------------------------------------------
// Final kernel: 1:1 read/write stream. final = pg*gen + (1-pg)*base, with
// in-chunk fixups for touched vocab slots.
// ---------------------------------------------------------------------------
__global__ __launch_bounds__(512) void final_kernel(
    const int* __restrict__ tok,
    const float* __restrict__ gen,
    float* __restrict__ out)
{
    const int row = blockIdx.x >> 1;       // b*T + t
    const int c   = blockIdx.x & (NCHUNK - 1);
    const int b   = row >> 9;
    const int tid = threadIdx.x;

    const float pg   = g_pg[row];
    const float base = g_base[row];
    const float omp  = 1.f - pg;
    const float pb   = omp * base;
    const int   lo   = c * CHUNK;

    // hoisted fixup state
    const int  lead = g_leader[b * Iv + tid];
    const int  v    = tok[b * Iv + tid];
    const bool act  = (lead == tid) && (v >= lo) && (v < lo + CHUNK);
    float gscat = 0.f, eb = 0.f;
    if (act) {
        gscat = __ldg(&gen[(long)row * Vv + v]);
        eb    = g_eb[(long)row * Iv + tid];
    }

    const float4* g4 = (const float4*)(gen + (long)row * Vv);
    float4* f4 = (float4*)(out + (long)row * Vv);
    const int q0 = lo >> 2, q1 = q0 + (CHUNK >> 2);

    #pragma unroll 4
    for (int q = q0 + tid; q < q1; q += 512) {
        float4 g = __ldcs(&g4[q]);
        float4 f;
        f.x = fmaf(pg, g.x, pb);
        f.y = fmaf(pg, g.y, pb);
        f.z = fmaf(pg, g.z, pb);
        f.w = fmaf(pg, g.w, pb);
        __stcs(&f4[q], f);
    }
    __syncthreads();                      // order fixup stores after stream

    if (act) {
        out[(long)row * Vv + v] = fmaf(pg, gscat, omp * eb);
    }
}

// ---------------------------------------------------------------------------
// Fill kernel: pure write stream. pointer = base everywhere + slot fixups.
// ---------------------------------------------------------------------------
__global__ __launch_bounds__(512) void fill_kernel(
    const int* __restrict__ tok,
    float* __restrict__ out)
{
    const int row = blockIdx.x >> 1;
    const int c   = blockIdx.x & (NCHUNK - 1);
    const int b   = row >> 9;
    const int tid = threadIdx.x;

    const float base = g_base[row];
    const int   lo   = c * CHUNK;

    const int  lead = g_leader[b * Iv + tid];
    const int  v    = tok[b * Iv + tid];
    const bool act  = (lead == tid) && (v >= lo) && (v < lo + CHUNK);
    float eb = 0.f;
    if (act) eb = g_eb[(long)row * Iv + tid];

    float4* p4 = (float4*)(out + (long)(Bv * Tv) * Vv + (long)row * Vv);
    const float4 pconst = make_float4(base, base, base, base);
    const int q0 = lo >> 2, q1 = q0 + (CHUNK >> 2);

    #pragma unroll 8
    for (int q = q0 + tid; q < q1; q += 512) {
        __stcs(&p4[q], pconst);
    }
    __syncthreads();

    if (act) {
        out[(long)(Bv * Tv) * Vv + (long)row * Vv + v] = eb;
    }
}

// ---------------------------------------------------------------------------
// Launch. Inputs: inp_tokens, tar_embedded, generator_output, enc_output,
// dec_state, attn_heads, W_pgen, b_pgen.
// Output: final (B,T,V) ++ pointer (B,T,V) ++ p_gen (B,T), float32.
// ---------------------------------------------------------------------------
extern "C" void kernel_launch(void* const* d_in, const int* in_sizes, int n_in,
                              void* d_out, int out_size) {
    const int*   tok  = (const int*)  d_in[0];
    const float* tar  = (const float*)d_in[1];
    const float* gen  = (const float*)d_in[2];
    const float* enc  = (const float*)d_in[3];
    const float* dec  = (const float*)d_in[4];
    const float* ah   = (const float*)d_in[5];
    const float* W    = (const float*)d_in[6];
    const float* bpg  = (const float*)d_in[7];
    float* out = (float*)d_out;

    prep_kernel<<<516, 128>>>(tok, enc, W);
    row_kernel<<<Bv * Tv, 512>>>(tok, tar, dec, ah, W, bpg, out);
    final_kernel<<<Bv * Tv * NCHUNK, 512>>>(tok, gen, out);
    fill_kernel<<<Bv * Tv * NCHUNK, 512>>>(tok, out);
}

// round 6
// speedup vs baseline: 1.1386x; 1.1386x over previous
#include <cuda_runtime.h>
#include <cuda_bf16.h>

#define Bv 4
#define Tv 512
#define Iv 512
#define Hv 8
#define Dv 512
#define Vv 32000
#define NCHUNK 2                 // stream blocks per row
#define CHUNK  (Vv / NCHUNK)     // 16000 floats per chunk
#define NQ4    (CHUNK / 4)       // 4000 float4 per chunk
#define HSZ 1024                 // dedup hash table slots

// scratch (allocation-free rule: __device__ globals)
__device__ int   g_leader[Bv * Iv];
__device__ float g_encW[Bv * Iv];
__device__ int   g_nu[Bv];
__device__ float g_pg[Bv * Tv];
__device__ float g_base[Bv * Tv];
__device__ float g_eb[Bv * Tv * Iv];   // e*base per (row, slot-owner i); 4MB

// ---------------------------------------------------------------------------
// Prep: blocks [0,512) encW (4 warps/block, one (b,i) row per warp, float4);
// blocks [512,516) per-batch dedup via smem hash.
// ---------------------------------------------------------------------------
__global__ __launch_bounds__(128) void prep_kernel(const int* __restrict__ tok,
                                                   const float* __restrict__ enc,
                                                   const float* __restrict__ W) {
    if (blockIdx.x < 512) {
        int warp = blockIdx.x * 4 + (threadIdx.x >> 5);    // 0..2047 = b*I+i
        int lane = threadIdx.x & 31;
        const float4* row = (const float4*)(enc + (long)warp * Dv);
        const float4* W4  = (const float4*)W;
        float acc = 0.f;
        #pragma unroll
        for (int k = 0; k < 4; k++) {
            int q = lane + 32 * k;              // 128 float4 per row
            float4 r = __ldg(&row[q]);
            float4 w = __ldg(&W4[q]);
            acc = fmaf(r.x, w.x, acc);
            acc = fmaf(r.y, w.y, acc);
            acc = fmaf(r.z, w.z, acc);
            acc = fmaf(r.w, w.w, acc);
        }
        #pragma unroll
        for (int o = 16; o; o >>= 1) acc += __shfl_down_sync(0xffffffffu, acc, o);
        if (lane == 0) g_encW[warp] = acc;
    } else {
        __shared__ int hkey[HSZ];
        __shared__ int hval[HSZ];
        __shared__ int cnt;
        int b = blockIdx.x - 512;
        int tid = threadIdx.x;
        if (tid == 0) cnt = 0;
        #pragma unroll
        for (int s = tid; s < HSZ; s += 128) { hkey[s] = -1; hval[s] = 0x7fffffff; }
        __syncthreads();
        int myslot[4];
        #pragma unroll
        for (int k = 0; k < 4; k++) {
            int i = tid + 128 * k;
            int me = tok[b * Iv + i];
            unsigned h = ((unsigned)me * 2654435761u) & (HSZ - 1);
            while (true) {
                int kk = atomicCAS(&hkey[h], -1, me);
                if (kk == -1 || kk == me) break;
                h = (h + 1) & (HSZ - 1);
            }
            myslot[k] = (int)h;
            atomicMin(&hval[h], i);
        }
        __syncthreads();
        int local = 0;
        #pragma unroll
        for (int k = 0; k < 4; k++) {
            int i = tid + 128 * k;
            int lead = hval[myslot[k]];
            g_leader[b * Iv + i] = lead;
            if (lead == i) local++;
        }
        atomicAdd(&cnt, local);
        __syncthreads();
        if (tid == 0) g_nu[b] = cnt;
    }
}

// ---------------------------------------------------------------------------
// Dual block reduction: sums v1 and v2 across 512 threads with one barrier set.
// ---------------------------------------------------------------------------
__device__ __forceinline__ void block_reduce_sum2(float v1, float v2,
                                                  float* s1, float* s2,
                                                  float& r1, float& r2) {
    int lane = threadIdx.x & 31;
    int w = threadIdx.x >> 5;
    #pragma unroll
    for (int o = 16; o; o >>= 1) {
        v1 += __shfl_down_sync(0xffffffffu, v1, o);
        v2 += __shfl_down_sync(0xffffffffu, v2, o);
    }
    if (lane == 0) { s1[w] = v1; s2[w] = v2; }
    __syncthreads();
    if (w == 0) {
        float x1 = (lane < 16) ? s1[lane] : 0.f;
        float x2 = (lane < 16) ? s2[lane] : 0.f;
        #pragma unroll
        for (int o = 8; o; o >>= 1) {
            x1 += __shfl_down_sync(0xffffffffu, x1, o);
            x2 += __shfl_down_sync(0xffffffffu, x2, o);
        }
        if (lane == 0) { s1[0] = x1; s2[0] = x2; }
    }
    __syncthreads();
    r1 = s1[0];
    r2 = s2[0];
}

// ---------------------------------------------------------------------------
// Row kernel: all latency/reduction work per (b,t) row; no bulk streaming.
// ---------------------------------------------------------------------------
__global__ __launch_bounds__(512) void row_kernel(
    const int* __restrict__ tok,
    const float* __restrict__ tar,
    const float* __restrict__ dec,
    const float* __restrict__ attn_heads,
    const float* __restrict__ W,
    const float* __restrict__ bpg,
    float* __restrict__ out)
{
    const int row = blockIdx.x;        // b*T + t
    const int b   = row >> 9;
    const int t   = row & 511;
    const int tid = threadIdx.x;

    __shared__ float ss[Iv];
    __shared__ float s1[32], s2[32];

    const int lead = g_leader[b * Iv + tid];
    ss[tid] = 0.f;

    // head-mean attention weight for column i = tid
    float w = 0.f;
    long base_a = ((long)b * Hv) * ((long)Tv * Iv) + (long)t * Iv + tid;
    #pragma unroll
    for (int h = 0; h < Hv; h++) w += attn_heads[base_a + (long)h * Tv * Iv];
    w *= 0.125f;

    __syncthreads();                   // ss zeroed
    atomicAdd(&ss[lead], w);

    // p_gen partials overlap the atomics
    float acc = w * g_encW[b * Iv + tid];
    acc = fmaf(dec[(long)row * Dv + tid], W[Dv + tid], acc);
    acc = fmaf(tar[(long)row * Dv + tid], W[2 * Dv + tid], acc);

    __syncthreads();                   // publish atomics

    const bool active = (lead == tid);
    float e = active ? expf(ss[tid]) : 0.f;

    float pgsum, esum;
    block_reduce_sum2(acc, e, s1, s2, pgsum, esum);

    const float denom = esum + (float)(Vv - g_nu[b]);
    const float base  = 1.f / denom;
    const float pg    = 1.f / (1.f + expf(-(pgsum + bpg[0])));

    g_eb[(long)row * Iv + tid] = e * base;     // 0 for inactive slots
    if (tid == 0) {
        g_pg[row]   = pg;
        g_base[row] = base;
        out[2L * Bv * Tv * Vv + row] = pg;     // p_gen (B,T)
    }
}

// ---------------------------------------------------------------------------
// Final kernel: read/write stream with batch-8 MLP. final = pg*gen+(1-pg)*base.
// Each thread handles 8 float4 (8 independent loads in flight, then 8 stores).
// ---------------------------------------------------------------------------
__global__ __launch_bounds__(512) void final_kernel(
    const int* __restrict__ tok,
    const float* __restrict__ gen,
    float* __restrict__ out)
{
    const int row = blockIdx.x >> 1;       // b*T + t
    const int c   = blockIdx.x & (NCHUNK - 1);
    const int b   = row >> 9;
    const int tid = threadIdx.x;

    const float pg   = g_pg[row];
    const float base = g_base[row];
    const float omp  = 1.f - pg;
    const float pb   = omp * base;
    const int   lo   = c * CHUNK;

    // hoisted fixup state
    const int  lead = g_leader[b * Iv + tid];
    const int  v    = tok[b * Iv + tid];
    const bool act  = (lead == tid) && (v >= lo) && (v < lo + CHUNK);
    float gscat = 0.f, eb = 0.f;
    if (act) {
        gscat = __ldg(&gen[(long)row * Vv + v]);
        eb    = g_eb[(long)row * Iv + tid];
    }

    const float4* g4 = (const float4*)(gen + (long)row * Vv);
    float4* f4 = (float4*)(out + (long)row * Vv);
    const int q0 = (lo >> 2) + tid;        // NQ4=4000 per chunk; 8*512=4096 covers it

    float4 r[8];
    bool ok[8];
    #pragma unroll
    for (int j = 0; j < 8; j++) {
        int q = q0 + j * 512;
        ok[j] = (j * 512 + tid) < NQ4;
        if (ok[j]) r[j] = __ldcs(&g4[q]);
    }
    #pragma unroll
    for (int j = 0; j < 8; j++) {
        if (ok[j]) {
            int q = q0 + j * 512;
            float4 f;
            f.x = fmaf(pg, r[j].x, pb);
            f.y = fmaf(pg, r[j].y, pb);
            f.z = fmaf(pg, r[j].z, pb);
            f.w = fmaf(pg, r[j].w, pb);
            __stcs(&f4[q], f);
        }
    }
    __syncthreads();                      // order fixup stores after stream

    if (act) {
        out[(long)row * Vv + v] = fmaf(pg, gscat, omp * eb);
    }
}

// ---------------------------------------------------------------------------
// Fill kernel: pure write stream. pointer = base everywhere + slot fixups.
// ---------------------------------------------------------------------------
__global__ __launch_bounds__(512) void fill_kernel(
    const int* __restrict__ tok,
    float* __restrict__ out)
{
    const int row = blockIdx.x >> 1;
    const int c   = blockIdx.x & (NCHUNK - 1);
    const int b   = row >> 9;
    const int tid = threadIdx.x;

    const float base = g_base[row];
    const int   lo   = c * CHUNK;

    const int  lead = g_leader[b * Iv + tid];
    const int  v    = tok[b * Iv + tid];
    const bool act  = (lead == tid) && (v >= lo) && (v < lo + CHUNK);
    float eb = 0.f;
    if (act) eb = g_eb[(long)row * Iv + tid];

    float4* p4 = (float4*)(out + (long)(Bv * Tv) * Vv + (long)row * Vv);
    const float4 pconst = make_float4(base, base, base, base);
    const int q0 = (lo >> 2) + tid;

    #pragma unroll
    for (int j = 0; j < 8; j++) {
        if ((j * 512 + tid) < NQ4) __stcs(&p4[q0 + j * 512], pconst);
    }
    __syncthreads();

    if (act) {
        out[(long)(Bv * Tv) * Vv + (long)row * Vv + v] = eb;
    }
}

// ---------------------------------------------------------------------------
// Launch. Inputs: inp_tokens, tar_embedded, generator_output, enc_output,
// dec_state, attn_heads, W_pgen, b_pgen.
// Output: final (B,T,V) ++ pointer (B,T,V) ++ p_gen (B,T), float32.
// ---------------------------------------------------------------------------
extern "C" void kernel_launch(void* const* d_in, const int* in_sizes, int n_in,
                              void* d_out, int out_size) {
    const int*   tok  = (const int*)  d_in[0];
    const float* tar  = (const float*)d_in[1];
    const float* gen  = (const float*)d_in[2];
    const float* enc  = (const float*)d_in[3];
    const float* dec  = (const float*)d_in[4];
    const float* ah   = (const float*)d_in[5];
    const float* W    = (const float*)d_in[6];
    const float* bpg  = (const float*)d_in[7];
    float* out = (float*)d_out;

    prep_kernel<<<516, 128>>>(tok, enc, W);
    row_kernel<<<Bv * Tv, 512>>>(tok, tar, dec, ah, W, bpg, out);
    final_kernel<<<Bv * Tv * NCHUNK, 512>>>(tok, gen, out);
    fill_kernel<<<Bv * Tv * NCHUNK, 512>>>(tok, out);
}

// round 7
// speedup vs baseline: 1.1996x; 1.0536x over previous
#include <cuda_runtime.h>
#include <cuda_bf16.h>

#define Bv 4
#define Tv 512
#define Iv 512
#define Hv 8
#define Dv 512
#define Vv 32000
#define NCHUNK 2                 // stream chunks per row
#define CHUNK  (Vv / NCHUNK)     // 16000 floats per chunk
#define NQ4    (CHUNK / 4)       // 4000 float4 per chunk
#define HSZ 1024                 // dedup hash table slots

// scratch (allocation-free rule: __device__ globals)
__device__ int   g_leader[Bv * Iv];
__device__ float g_encW[Bv * Iv];
__device__ int   g_nu[Bv];
__device__ float g_pg[Bv * Tv];
__device__ float g_base[Bv * Tv];
__device__ float g_eb[Bv * Tv * Iv];   // e*base per (row, slot-owner i); 4MB

// ---------------------------------------------------------------------------
// Prep: blocks [0,512) encW (4 warps/block, one (b,i) row per warp, float4);
// blocks [512,516) per-batch dedup via smem hash.
// ---------------------------------------------------------------------------
__global__ __launch_bounds__(128) void prep_kernel(const int* __restrict__ tok,
                                                   const float* __restrict__ enc,
                                                   const float* __restrict__ W) {
    if (blockIdx.x < 512) {
        int warp = blockIdx.x * 4 + (threadIdx.x >> 5);    // 0..2047 = b*I+i
        int lane = threadIdx.x & 31;
        const float4* row = (const float4*)(enc + (long)warp * Dv);
        const float4* W4  = (const float4*)W;
        float acc = 0.f;
        #pragma unroll
        for (int k = 0; k < 4; k++) {
            int q = lane + 32 * k;              // 128 float4 per row
            float4 r = __ldg(&row[q]);
            float4 w = __ldg(&W4[q]);
            acc = fmaf(r.x, w.x, acc);
            acc = fmaf(r.y, w.y, acc);
            acc = fmaf(r.z, w.z, acc);
            acc = fmaf(r.w, w.w, acc);
        }
        #pragma unroll
        for (int o = 16; o; o >>= 1) acc += __shfl_down_sync(0xffffffffu, acc, o);
        if (lane == 0) g_encW[warp] = acc;
    } else {
        __shared__ int hkey[HSZ];
        __shared__ int hval[HSZ];
        __shared__ int cnt;
        int b = blockIdx.x - 512;
        int tid = threadIdx.x;
        if (tid == 0) cnt = 0;
        #pragma unroll
        for (int s = tid; s < HSZ; s += 128) { hkey[s] = -1; hval[s] = 0x7fffffff; }
        __syncthreads();
        int myslot[4];
        #pragma unroll
        for (int k = 0; k < 4; k++) {
            int i = tid + 128 * k;
            int me = tok[b * Iv + i];
            unsigned h = ((unsigned)me * 2654435761u) & (HSZ - 1);
            while (true) {
                int kk = atomicCAS(&hkey[h], -1, me);
                if (kk == -1 || kk == me) break;
                h = (h + 1) & (HSZ - 1);
            }
            myslot[k] = (int)h;
            atomicMin(&hval[h], i);
        }
        __syncthreads();
        int local = 0;
        #pragma unroll
        for (int k = 0; k < 4; k++) {
            int i = tid + 128 * k;
            int lead = hval[myslot[k]];
            g_leader[b * Iv + i] = lead;
            if (lead == i) local++;
        }
        atomicAdd(&cnt, local);
        __syncthreads();
        if (tid == 0) g_nu[b] = cnt;
    }
}

// ---------------------------------------------------------------------------
// Dual block reduction: sums v1 and v2 across 512 threads with one barrier set.
// ---------------------------------------------------------------------------
__device__ __forceinline__ void block_reduce_sum2(float v1, float v2,
                                                  float* s1, float* s2,
                                                  float& r1, float& r2) {
    int lane = threadIdx.x & 31;
    int w = threadIdx.x >> 5;
    #pragma unroll
    for (int o = 16; o; o >>= 1) {
        v1 += __shfl_down_sync(0xffffffffu, v1, o);
        v2 += __shfl_down_sync(0xffffffffu, v2, o);
    }
    if (lane == 0) { s1[w] = v1; s2[w] = v2; }
    __syncthreads();
    if (w == 0) {
        float x1 = (lane < 16) ? s1[lane] : 0.f;
        float x2 = (lane < 16) ? s2[lane] : 0.f;
        #pragma unroll
        for (int o = 8; o; o >>= 1) {
            x1 += __shfl_down_sync(0xffffffffu, x1, o);
            x2 += __shfl_down_sync(0xffffffffu, x2, o);
        }
        if (lane == 0) { s1[0] = x1; s2[0] = x2; }
    }
    __syncthreads();
    r1 = s1[0];
    r2 = s2[0];
}

// ---------------------------------------------------------------------------
// Row kernel (PDL consumer of prep): prefetch attn planes (pure inputs) BEFORE
// the grid dependency sync, then use prep outputs.
// ---------------------------------------------------------------------------
__global__ __launch_bounds__(512) void row_kernel(
    const int* __restrict__ tok,
    const float* __restrict__ tar,
    const float* __restrict__ dec,
    const float* __restrict__ attn_heads,
    const float* __restrict__ W,
    const float* __restrict__ bpg,
    float* __restrict__ out)
{
    const int row = blockIdx.x;        // b*T + t
    const int b   = row >> 9;
    const int t   = row & 511;
    const int tid = threadIdx.x;

    __shared__ float ss[Iv];
    __shared__ float s1[32], s2[32];

    ss[tid] = 0.f;

    // prefetch inputs (not produced by prep) while prep finishes
    float a[Hv];
    long base_a = ((long)b * Hv) * ((long)Tv * Iv) + (long)t * Iv + tid;
    #pragma unroll
    for (int h = 0; h < Hv; h++) a[h] = __ldg(&attn_heads[base_a + (long)h * Tv * Iv]);
    float dv = __ldg(&dec[(long)row * Dv + tid]);
    float tv = __ldg(&tar[(long)row * Dv + tid]);
    float w1 = __ldg(&W[Dv + tid]);
    float w2 = __ldg(&W[2 * Dv + tid]);

    cudaGridDependencySynchronize();   // prep's g_leader/g_encW/g_nu now visible

    const int lead = g_leader[b * Iv + tid];

    float w = 0.f;
    #pragma unroll
    for (int h = 0; h < Hv; h++) w += a[h];
    w *= 0.125f;

    __syncthreads();                   // ss zeroed
    atomicAdd(&ss[lead], w);

    float acc = w * g_encW[b * Iv + tid];
    acc = fmaf(dv, w1, acc);
    acc = fmaf(tv, w2, acc);

    __syncthreads();                   // publish atomics

    const bool active = (lead == tid);
    float e = active ? expf(ss[tid]) : 0.f;

    float pgsum, esum;
    block_reduce_sum2(acc, e, s1, s2, pgsum, esum);

    const float denom = esum + (float)(Vv - g_nu[b]);
    const float base  = 1.f / denom;
    const float pg    = 1.f / (1.f + expf(-(pgsum + bpg[0])));

    g_eb[(long)row * Iv + tid] = e * base;     // 0 for inactive slots
    if (tid == 0) {
        g_pg[row]   = pg;
        g_base[row] = base;
        out[2L * Bv * Tv * Vv + row] = pg;     // p_gen (B,T)
    }
}

// ---------------------------------------------------------------------------
// Stream kernel (PDL consumer of row). Role by blockIdx parity:
//  role 0 (final): batch-8 ldcs of gen issued BEFORE the dependency sync —
//                  row's runtime hides behind the load wave.
//  role 1 (fill):  pure write stream pointer = base.
// ---------------------------------------------------------------------------
__global__ __launch_bounds__(512) void stream_kernel(
    const int* __restrict__ tok,
    const float* __restrict__ gen,
    float* __restrict__ out)
{
    const int role = blockIdx.x & 1;
    const int rc   = blockIdx.x >> 1;      // 0..4095
    const int row  = rc >> 1;              // b*T + t
    const int c    = rc & (NCHUNK - 1);
    const int b    = row >> 9;
    const int tid  = threadIdx.x;
    const int lo   = c * CHUNK;

    const int v = __ldg(&tok[b * Iv + tid]);   // input: safe pre-sync

    if (role == 0) {
        // ---- final = pg*gen + (1-pg)*base ----
        const float4* g4 = (const float4*)(gen + (long)row * Vv);
        float4* f4 = (float4*)(out + (long)row * Vv);
        const int q0 = (lo >> 2) + tid;

        float4 r[8];
        bool ok[8];
        #pragma unroll
        for (int j = 0; j < 8; j++) {
            ok[j] = (j * 512 + tid) < NQ4;
            if (ok[j]) r[j] = __ldcs(&g4[q0 + j * 512]);
        }

        cudaGridDependencySynchronize();   // row's pg/base/eb now visible

        const float pg   = g_pg[row];
        const float base = g_base[row];
        const float omp  = 1.f - pg;
        const float pb   = omp * base;

        const int  lead = g_leader[b * Iv + tid];
        const bool act  = (lead == tid) && (v >= lo) && (v < lo + CHUNK);
        float gscat = 0.f, eb = 0.f;
        if (act) {
            gscat = __ldg(&gen[(long)row * Vv + v]);
            eb    = g_eb[(long)row * Iv + tid];
        }

        #pragma unroll
        for (int j = 0; j < 8; j++) {
            if (ok[j]) {
                float4 f;
                f.x = fmaf(pg, r[j].x, pb);
                f.y = fmaf(pg, r[j].y, pb);
                f.z = fmaf(pg, r[j].z, pb);
                f.w = fmaf(pg, r[j].w, pb);
                __stcs(&f4[q0 + j * 512], f);
            }
        }
        __syncthreads();                  // order fixup after stream
        if (act) out[(long)row * Vv + v] = fmaf(pg, gscat, omp * eb);
    } else {
        // ---- pointer = base (+ slot fixups) ----
        cudaGridDependencySynchronize();

        const float base = g_base[row];
        const int  lead = g_leader[b * Iv + tid];
        const bool act  = (lead == tid) && (v >= lo) && (v < lo + CHUNK);
        float eb = 0.f;
        if (act) eb = g_eb[(long)row * Iv + tid];

        float4* p4 = (float4*)(out + (long)(Bv * Tv) * Vv + (long)row * Vv);
        const float4 pconst = make_float4(base, base, base, base);
        const int q0 = (lo >> 2) + tid;

        #pragma unroll
        for (int j = 0; j < 8; j++) {
            if ((j * 512 + tid) < NQ4) __stcs(&p4[q0 + j * 512], pconst);
        }
        __syncthreads();
        if (act) out[(long)(Bv * Tv) * Vv + (long)row * Vv + v] = eb;
    }
}

// ---------------------------------------------------------------------------
// Launch with PDL chaining. Inputs: inp_tokens, tar_embedded,
// generator_output, enc_output, dec_state, attn_heads, W_pgen, b_pgen.
// ---------------------------------------------------------------------------
extern "C" void kernel_launch(void* const* d_in, const int* in_sizes, int n_in,
                              void* d_out, int out_size) {
    const int*   tok  = (const int*)  d_in[0];
    const float* tar  = (const float*)d_in[1];
    const float* gen  = (const float*)d_in[2];
    const float* enc  = (const float*)d_in[3];
    const float* dec  = (const float*)d_in[4];
    const float* ah   = (const float*)d_in[5];
    const float* W    = (const float*)d_in[6];
    const float* bpg  = (const float*)d_in[7];
    float* out = (float*)d_out;

    prep_kernel<<<516, 128>>>(tok, enc, W);

    cudaLaunchAttribute attr[1];
    attr[0].id = cudaLaunchAttributeProgrammaticStreamSerialization;
    attr[0].val.programmaticStreamSerializationAllowed = 1;

    {
        cudaLaunchConfig_t cfg = {};
        cfg.gridDim  = dim3(Bv * Tv);
        cfg.blockDim = dim3(512);
        cfg.attrs    = attr;
        cfg.numAttrs = 1;
        cudaLaunchKernelEx(&cfg, row_kernel, tok, tar, dec, ah, W, bpg, out);
    }
    {
        cudaLaunchConfig_t cfg = {};
        cfg.gridDim  = dim3(2 * Bv * Tv * NCHUNK);
        cfg.blockDim = dim3(512);
        cfg.attrs    = attr;
        cfg.numAttrs = 1;
        cudaLaunchKernelEx(&cfg, stream_kernel, tok, gen, out);
    }
}